// round 2
// baseline (speedup 1.0000x reference)
#include <cuda_runtime.h>
#include <cuda_bf16.h>
#include <math.h>

// Problem constants
// B=16, C=22, L=3000, D=64, D2=256, E=8, T=4, K=13
// Only token n=0 of the final output matters -> only hLN[:,0:7,:] is needed.

__device__ float g_h[16 * 6 * 64];       // pooled conv features [b][p][d]
__device__ float g_hln[16 * 7 * 64];     // LN'd tokens 0..6 [b][n][d]
__device__ float g_UT[448 * 256];        // U transposed: [(k*64+d)][o]
__device__ float g_B0[256];              // bias fold: sum_{c,d} W[o,c,d]*ds_conv_b[c]

__device__ __forceinline__ float gelu_exact(float x) {
    return 0.5f * x * (1.0f + erff(x * 0.70710678118654752f));
}

// ---------------------------------------------------------------------------
// K1: conv1d(stride2,pad6) + GELU + maxpool(3,3) for pooled positions 0..5
// grid (6, 16) = (p, b), 192 threads = (qi in 0..2) x (d in 0..63)
// ---------------------------------------------------------------------------
__global__ void k1_conv_pool(const float* __restrict__ x,
                             const float* __restrict__ cw,
                             const float* __restrict__ cb) {
    __shared__ float xs[22][23];
    __shared__ float cv[3][64];
    int p = blockIdx.x, b = blockIdx.y, t = threadIdx.x;
    int base = 6 * p - 6;
    for (int l = t; l < 22 * 23; l += 192) {
        int c = l / 23, j = l - c * 23;
        int xi = base + j;
        xs[c][j] = (xi >= 0) ? x[(b * 22 + c) * 3000 + xi] : 0.f;
    }
    __syncthreads();
    int qi = t / 64, d = t & 63;   // t < 192
    float acc = cb[d];
    const float* wp = cw + d * 286;
    #pragma unroll
    for (int c = 0; c < 22; c++) {
        #pragma unroll
        for (int k = 0; k < 13; k++) {
            acc += __ldg(wp + c * 13 + k) * xs[c][2 * qi + k];
        }
    }
    cv[qi][d] = gelu_exact(acc);
    __syncthreads();
    if (t < 64) {
        float m = fmaxf(fmaxf(cv[0][t], cv[1][t]), cv[2][t]);
        g_h[(b * 6 + p) * 64 + t] = m;
    }
}

// ---------------------------------------------------------------------------
// K2: LayerNorm over D=64 for tokens n=0..6 (n=0 = cls token)
// grid 16 (b), 224 threads (7 warps, one per token row)
// ---------------------------------------------------------------------------
__global__ void k2_ln(const float* __restrict__ cls,
                      const float* __restrict__ tg,
                      const float* __restrict__ tb) {
    int b = blockIdx.x, t = threadIdx.x;
    int w = t >> 5, lane = t & 31;
    if (w >= 7) return;
    float v0, v1;
    if (w == 0) { v0 = cls[lane]; v1 = cls[lane + 32]; }
    else {
        const float* p = g_h + (b * 6 + (w - 1)) * 64;
        v0 = p[lane]; v1 = p[lane + 32];
    }
    float s = v0 + v1;
    #pragma unroll
    for (int off = 16; off; off >>= 1) s += __shfl_xor_sync(0xffffffffu, s, off);
    float mean = s * (1.f / 64.f);
    float d0 = v0 - mean, d1 = v1 - mean;
    float q = d0 * d0 + d1 * d1;
    #pragma unroll
    for (int off = 16; off; off >>= 1) q += __shfl_xor_sync(0xffffffffu, q, off);
    float rstd = rsqrtf(q * (1.f / 64.f) + 1e-5f);
    float* dst = g_hln + b * 448 + w * 64;
    dst[lane]      = d0 * rstd * tg[lane]      + tb[lane];
    dst[lane + 32] = d1 * rstd * tg[lane + 32] + tb[lane + 32];
}

// ---------------------------------------------------------------------------
// K3: fold ds_conv into ds_comp_w:
//   U[o,k,d] = sum_c W[o,c,d] * w1[c, 6+k]   (k = 0..6)
//   B0[o]    = sum_{c,d} W[o,c,d] * ds_conv_b[c]
// Streams W (16.8MB) exactly once. grid 256 (o), 256 threads
// ---------------------------------------------------------------------------
__global__ void k3_fold(const float* __restrict__ W,
                        const float* __restrict__ w1,
                        const float* __restrict__ dcb) {
    __shared__ float w1s[256 * 7];
    __shared__ float chunk[8192];   // 128 c x 64 d
    __shared__ float bred[64];
    int o = blockIdx.x, t = threadIdx.x;
    for (int l = t; l < 1792; l += 256) {
        int c = l / 7, k = l - c * 7;
        w1s[l] = w1[c * 13 + 6 + k];
    }
    int d = t & 63, kq = t >> 6;   // kq in 0..3 -> k = kq and kq+4
    float u0 = 0.f, u1 = 0.f, bacc = 0.f;
    const float* Wo = W + (long)o * 16384;
    for (int half = 0; half < 2; half++) {
        __syncthreads();
        const float4* src = (const float4*)(Wo + half * 8192);
        float4* dst4 = (float4*)chunk;
        for (int l = t; l < 2048; l += 256) dst4[l] = __ldg(src + l);
        __syncthreads();
        int c0 = half * 128;
        #pragma unroll 4
        for (int c = 0; c < 128; c++) {
            float s = chunk[c * 64 + d];
            const float* wrow = w1s + (c0 + c) * 7;
            u0 += s * wrow[kq];
            if (kq < 3) u1 += s * wrow[kq + 4];
            if (kq == 0) bacc += s * __ldg(dcb + c0 + c);
        }
    }
    g_UT[(kq * 64 + d) * 256 + o] = u0;
    if (kq < 3) g_UT[((kq + 4) * 64 + d) * 256 + o] = u1;
    if (kq == 0) bred[d] = bacc;
    __syncthreads();
    if (t < 32) {
        float s = bred[t] + bred[t + 32];
        #pragma unroll
        for (int off = 16; off; off >>= 1) s += __shfl_xor_sync(0xffffffffu, s, off);
        if (t == 0) g_B0[o] = s;
    }
}

// ---------------------------------------------------------------------------
// K4: per-batch epilogue. grid 16 (b), 256 threads.
//   tokens_pre[o] = B0[o] + ds_comp_b[o] + sum_i UT[i][o]*hln[b][i]
//   tokens = gelu(LN(tokens_pre; ds_g, ds_b))
//   top-2 gate -> 2 expert GEMVs + universal GEMV -> final LN -> out[b]
// ---------------------------------------------------------------------------
__device__ __forceinline__ float block_sum_256(float v, float* red) {
    #pragma unroll
    for (int off = 16; off; off >>= 1) v += __shfl_xor_sync(0xffffffffu, v, off);
    int w = threadIdx.x >> 5;
    if ((threadIdx.x & 31) == 0) red[w] = v;
    __syncthreads();
    if (threadIdx.x < 32) {
        float x = (threadIdx.x < 8) ? red[threadIdx.x] : 0.f;
        #pragma unroll
        for (int off = 4; off; off >>= 1) x += __shfl_xor_sync(0xffffffffu, x, off);
        if (threadIdx.x == 0) red[0] = x;
    }
    __syncthreads();
    float r = red[0];
    __syncthreads();
    return r;
}

__global__ void k4_moe(const int* __restrict__ task_ids,
                       const float* __restrict__ task_embed,
                       const float* __restrict__ dcompb,
                       const float* __restrict__ ds_g,
                       const float* __restrict__ ds_b,
                       const float* __restrict__ gate_w,
                       const float* __restrict__ gate_b,
                       const float* __restrict__ exp_w,
                       const float* __restrict__ exp_b,
                       const float* __restrict__ uni_w,
                       const float* __restrict__ uni_b,
                       const float* __restrict__ out_g,
                       const float* __restrict__ out_b,
                       float* __restrict__ out) {
    int b = blockIdx.x, t = threadIdx.x;
    __shared__ float hs[448];
    __shared__ float part[4][256];
    __shared__ float tok[256];
    __shared__ float ybuf[3][256];
    __shared__ float red[32];
    __shared__ float gsh[8];
    __shared__ int esel[2];
    __shared__ float gcoef[3];

    for (int i = t; i < 448; i += 256) hs[i] = g_hln[b * 448 + i];
    __syncthreads();

    // tokens_pre GEMV: UT [448][256], 4 groups split the i-dim, float4 over o
    {
        int grp = t >> 6, o4 = (t & 63) * 4;
        float4 acc = make_float4(0.f, 0.f, 0.f, 0.f);
        const float* Up = g_UT + grp * 112 * 256;
        const float* hp = hs + grp * 112;
        #pragma unroll 4
        for (int i = 0; i < 112; i++) {
            float h = hp[i];
            float4 w4 = *(const float4*)(Up + i * 256 + o4);
            acc.x += h * w4.x; acc.y += h * w4.y;
            acc.z += h * w4.z; acc.w += h * w4.w;
        }
        part[grp][o4 + 0] = acc.x; part[grp][o4 + 1] = acc.y;
        part[grp][o4 + 2] = acc.z; part[grp][o4 + 3] = acc.w;
    }
    __syncthreads();

    float tp = part[0][t] + part[1][t] + part[2][t] + part[3][t]
             + g_B0[t] + dcompb[t];

    // LN over 256 (ds_g, ds_b) then GELU -> tokens
    float mean = block_sum_256(tp, red) * (1.f / 256.f);
    float dv = tp - mean;
    float var = block_sum_256(dv * dv, red) * (1.f / 256.f);
    float rstd = rsqrtf(var + 1e-5f);
    float tv = gelu_exact(dv * rstd * ds_g[t] + ds_b[t]);
    tok[t] = tv;
    __syncthreads();

    // gating: warp e computes logit e (8 warps)
    {
        int w = t >> 5, lane = t & 31;
        int tid_task = task_ids[b];
        const float* te = task_embed + tid_task * 256;
        float s = 0.f;
        for (int o = lane; o < 256; o += 32) {
            s += tok[o] * __ldg(gate_w + o * 8 + w);
            s += __ldg(te + o) * __ldg(gate_w + (256 + o) * 8 + w);
        }
        #pragma unroll
        for (int off = 16; off; off >>= 1) s += __shfl_xor_sync(0xffffffffu, s, off);
        if (lane == 0) gsh[w] = s + gate_b[w];
    }
    __syncthreads();
    if (t == 0) {
        float v1 = -1e30f; int e1 = 0;
        #pragma unroll
        for (int e = 0; e < 8; e++) if (gsh[e] > v1) { v1 = gsh[e]; e1 = e; }
        float v2 = -1e30f; int e2 = 0;
        #pragma unroll
        for (int e = 0; e < 8; e++) if (e != e1 && gsh[e] > v2) { v2 = gsh[e]; e2 = e; }
        float g1 = 1.f / (1.f + expf(v2 - v1));
        esel[0] = e1; esel[1] = e2;
        gcoef[0] = g1; gcoef[1] = 1.f - g1; gcoef[2] = 1.f - g1;  // omega = 1 - max gate
    }
    __syncthreads();

    // 3 GEMVs (expert1, expert2, universal), 64 threads each, float4 over f
    if (t < 192) {
        int grp = t >> 6, f4 = (t & 63) * 4;
        const float* Wb; const float* Bb;
        if (grp < 2) {
            Wb = exp_w + (long)esel[grp] * 65536;
            Bb = exp_b + esel[grp] * 256;
        } else {
            Wb = uni_w; Bb = uni_b;
        }
        float4 acc = make_float4(0.f, 0.f, 0.f, 0.f);
        #pragma unroll 4
        for (int d = 0; d < 256; d++) {
            float tv2 = tok[d];
            float4 w4 = __ldg((const float4*)(Wb + d * 256 + f4));
            acc.x += tv2 * w4.x; acc.y += tv2 * w4.y;
            acc.z += tv2 * w4.z; acc.w += tv2 * w4.w;
        }
        ybuf[grp][f4 + 0] = gelu_exact(acc.x + Bb[f4 + 0]);
        ybuf[grp][f4 + 1] = gelu_exact(acc.y + Bb[f4 + 1]);
        ybuf[grp][f4 + 2] = gelu_exact(acc.z + Bb[f4 + 2]);
        ybuf[grp][f4 + 3] = gelu_exact(acc.w + Bb[f4 + 3]);
    }
    __syncthreads();

    float val = gcoef[0] * ybuf[0][t] + gcoef[1] * ybuf[1][t]
              + gcoef[2] * ybuf[2][t];

    // final LN (out_g, out_b)
    float m2 = block_sum_256(val, red) * (1.f / 256.f);
    float d2 = val - m2;
    float v2s = block_sum_256(d2 * d2, red) * (1.f / 256.f);
    float rs2 = rsqrtf(v2s + 1e-5f);
    out[b * 256 + t] = d2 * rs2 * out_g[t] + out_b[t];
}

// ---------------------------------------------------------------------------
extern "C" void kernel_launch(void* const* d_in, const int* in_sizes, int n_in,
                              void* d_out, int out_size) {
    const float* x_stream   = (const float*)d_in[0];
    const int*   task_ids   = (const int*)  d_in[1];
    const float* conv_w     = (const float*)d_in[2];
    const float* conv_b     = (const float*)d_in[3];
    const float* cls_token  = (const float*)d_in[4];
    const float* tok_g      = (const float*)d_in[5];
    const float* tok_b      = (const float*)d_in[6];
    const float* ds_conv_w  = (const float*)d_in[7];
    const float* ds_conv_b  = (const float*)d_in[8];
    const float* ds_comp_w  = (const float*)d_in[9];
    const float* ds_comp_b  = (const float*)d_in[10];
    const float* ds_g       = (const float*)d_in[11];
    const float* ds_b       = (const float*)d_in[12];
    const float* task_embed = (const float*)d_in[13];
    const float* gate_w     = (const float*)d_in[14];
    const float* gate_b     = (const float*)d_in[15];
    const float* exp_w      = (const float*)d_in[16];
    const float* exp_b      = (const float*)d_in[17];
    const float* uni_w      = (const float*)d_in[18];
    const float* uni_b      = (const float*)d_in[19];
    const float* out_g      = (const float*)d_in[20];
    const float* out_b      = (const float*)d_in[21];
    float* out = (float*)d_out;

    k1_conv_pool<<<dim3(6, 16), 192>>>(x_stream, conv_w, conv_b);
    k2_ln<<<16, 224>>>(cls_token, tok_g, tok_b);
    k3_fold<<<256, 256>>>(ds_comp_w, ds_conv_w, ds_conv_b);
    k4_moe<<<16, 256>>>(task_ids, task_embed, ds_comp_b, ds_g, ds_b,
                        gate_w, gate_b, exp_w, exp_b, uni_w, uni_b,
                        out_g, out_b, out);
}

// round 3
// speedup vs baseline: 1.9827x; 1.9827x over previous
#include <cuda_runtime.h>
#include <cuda_bf16.h>
#include <math.h>

// B=16, C=22, L=3000, D=64, D2=256, E=8, T=4, K=13
// Only output token n=0 matters -> only tokens n=0..6 (conv q=0..17, x[:, :, 0..40]).

__device__ float g_cwT[286 * 64];        // transposed conv_w: [(c*13+k)][d]
__device__ float g_h[16 * 6 * 64];       // pooled conv features [b][p][d]
__device__ float g_UT[448 * 256];        // folded weights: [(k*64+d)][o]
__device__ float g_B0[256];              // bias fold
__device__ float g_tok[16 * 256];        // MoE input tokens
__device__ int   g_esel[16 * 2];         // selected experts per b
__device__ float g_gc[16 * 4];           // gate coefs {g1, 1-g1, omega}
__device__ float g_y[16 * 3 * 256];      // GEMV outputs (e1, e2, universal)

__device__ __forceinline__ float gelu_exact(float x) {
    return 0.5f * x * (1.0f + erff(x * 0.70710678118654752f));
}

// ---------------------------------------------------------------------------
// K0: transpose conv_w [64][286] -> g_cwT [286][64] for coalesced k1 reads
// ---------------------------------------------------------------------------
__global__ void k0_transpose(const float* __restrict__ cw) {
    int idx = blockIdx.x * 256 + threadIdx.x;
    if (idx < 286 * 64) {
        int ck = idx >> 6, d = idx & 63;
        g_cwT[idx] = __ldg(cw + d * 286 + ck);
    }
}

// ---------------------------------------------------------------------------
// K1: conv1d(stride2,pad6) + GELU + maxpool(3,3) for pooled positions 0..5
// grid (6, 16) = (p, b), 192 threads = (qi 0..2) x (d 0..63)
// ---------------------------------------------------------------------------
__global__ void k1_conv_pool(const float* __restrict__ x,
                             const float* __restrict__ cb) {
    __shared__ float xs[22][23];
    __shared__ float cv[3][64];
    int p = blockIdx.x, b = blockIdx.y, t = threadIdx.x;
    int base = 6 * p - 6;
    for (int l = t; l < 22 * 23; l += 192) {
        int c = l / 23, j = l - c * 23;
        int xi = base + j;
        xs[c][j] = (xi >= 0) ? x[(b * 22 + c) * 3000 + xi] : 0.f;
    }
    __syncthreads();
    int qi = t / 64, d = t & 63;
    float acc = cb[d];
    #pragma unroll
    for (int c = 0; c < 22; c++) {
        #pragma unroll
        for (int k = 0; k < 13; k++) {
            // coalesced: consecutive d across warp
            acc += __ldg(g_cwT + (c * 13 + k) * 64 + d) * xs[c][2 * qi + k];
        }
    }
    cv[qi][d] = gelu_exact(acc);
    __syncthreads();
    if (t < 64) {
        float m = fmaxf(fmaxf(cv[0][t], cv[1][t]), cv[2][t]);
        g_h[(b * 6 + p) * 64 + t] = m;
    }
}

// ---------------------------------------------------------------------------
// K3: fold ds_conv into ds_comp_w (streams W = 16.8MB exactly once)
//   U[o,k,d] = sum_c W[o,c,d] * w1[c, 6+k]   (k = 0..6)
//   B0[o]    = sum_{c,d} W[o,c,d] * ds_conv_b[c]
// grid 256 (o), 256 threads
// ---------------------------------------------------------------------------
__global__ void k3_fold(const float* __restrict__ W,
                        const float* __restrict__ w1,
                        const float* __restrict__ dcb) {
    __shared__ float w1s[256 * 7];
    __shared__ float chunk[8192];   // 128 c x 64 d
    __shared__ float bred[64];
    int o = blockIdx.x, t = threadIdx.x;
    for (int l = t; l < 1792; l += 256) {
        int c = l / 7, k = l - c * 7;
        w1s[l] = w1[c * 13 + 6 + k];
    }
    int d = t & 63, kq = t >> 6;   // kq -> k = kq and kq+4
    float u0 = 0.f, u1 = 0.f, bacc = 0.f;
    const float* Wo = W + (long)o * 16384;
    for (int half = 0; half < 2; half++) {
        __syncthreads();
        const float4* src = (const float4*)(Wo + half * 8192);
        float4* dst4 = (float4*)chunk;
        #pragma unroll
        for (int l0 = 0; l0 < 2048; l0 += 256) dst4[l0 + t] = __ldg(src + l0 + t);
        __syncthreads();
        int c0 = half * 128;
        #pragma unroll 4
        for (int c = 0; c < 128; c++) {
            float s = chunk[c * 64 + d];
            const float* wrow = w1s + (c0 + c) * 7;
            u0 += s * wrow[kq];
            if (kq < 3) u1 += s * wrow[kq + 4];
            if (kq == 0) bacc += s * __ldg(dcb + c0 + c);
        }
    }
    g_UT[(kq * 64 + d) * 256 + o] = u0;
    if (kq < 3) g_UT[((kq + 4) * 64 + d) * 256 + o] = u1;
    if (kq == 0) bred[d] = bacc;
    __syncthreads();
    if (t < 32) {
        float s = bred[t] + bred[t + 32];
        #pragma unroll
        for (int off = 16; off; off >>= 1) s += __shfl_xor_sync(0xffffffffu, s, off);
        if (t == 0) g_B0[o] = s;
    }
}

// ---------------------------------------------------------------------------
// block-wide sums
// ---------------------------------------------------------------------------
__device__ __forceinline__ float bsum512(float v, float* red) {
    #pragma unroll
    for (int off = 16; off; off >>= 1) v += __shfl_xor_sync(0xffffffffu, v, off);
    int w = threadIdx.x >> 5;
    if ((threadIdx.x & 31) == 0) red[w] = v;
    __syncthreads();
    if (threadIdx.x < 32) {
        float x = (threadIdx.x < 16) ? red[threadIdx.x] : 0.f;
        #pragma unroll
        for (int off = 8; off; off >>= 1) x += __shfl_xor_sync(0xffffffffu, x, off);
        if (threadIdx.x == 0) red[0] = x;
    }
    __syncthreads();
    float r = red[0];
    __syncthreads();
    return r;
}

__device__ __forceinline__ float bsum256(float v, float* red) {
    #pragma unroll
    for (int off = 16; off; off >>= 1) v += __shfl_xor_sync(0xffffffffu, v, off);
    int w = threadIdx.x >> 5;
    if ((threadIdx.x & 31) == 0) red[w] = v;
    __syncthreads();
    if (threadIdx.x < 32) {
        float x = (threadIdx.x < 8) ? red[threadIdx.x] : 0.f;
        #pragma unroll
        for (int off = 4; off; off >>= 1) x += __shfl_xor_sync(0xffffffffu, x, off);
        if (threadIdx.x == 0) red[0] = x;
    }
    __syncthreads();
    float r = red[0];
    __syncthreads();
    return r;
}

// ---------------------------------------------------------------------------
// K4a: token LN (merged old k2) + tokens_pre GEMV + LN + GELU + gating.
// grid 16 (b), 512 threads
// ---------------------------------------------------------------------------
__global__ void k4a(const float* __restrict__ cls,
                    const float* __restrict__ tg,
                    const float* __restrict__ tb,
                    const int* __restrict__ task_ids,
                    const float* __restrict__ task_embed,
                    const float* __restrict__ dcompb,
                    const float* __restrict__ ds_g,
                    const float* __restrict__ ds_b,
                    const float* __restrict__ gate_w,
                    const float* __restrict__ gate_b) {
    int b = blockIdx.x, t = threadIdx.x;
    int w = t >> 5, lane = t & 31;
    __shared__ float hs[448];
    __shared__ float part[8][256];
    __shared__ float red[32];
    __shared__ float gsh[8];

    // --- LN of 7 tokens over D=64 (warp per token) ---
    if (w < 7) {
        float v0, v1;
        if (w == 0) { v0 = cls[lane]; v1 = cls[lane + 32]; }
        else {
            const float* p = g_h + (b * 6 + (w - 1)) * 64;
            v0 = p[lane]; v1 = p[lane + 32];
        }
        float s = v0 + v1;
        #pragma unroll
        for (int off = 16; off; off >>= 1) s += __shfl_xor_sync(0xffffffffu, s, off);
        float mean = s * (1.f / 64.f);
        float d0 = v0 - mean, d1 = v1 - mean;
        float q = d0 * d0 + d1 * d1;
        #pragma unroll
        for (int off = 16; off; off >>= 1) q += __shfl_xor_sync(0xffffffffu, q, off);
        float rstd = rsqrtf(q * (1.f / 64.f) + 1e-5f);
        hs[w * 64 + lane]      = d0 * rstd * tg[lane]      + tb[lane];
        hs[w * 64 + lane + 32] = d1 * rstd * tg[lane + 32] + tb[lane + 32];
    }
    __syncthreads();

    // --- tokens_pre GEMV: 8 groups x 64 threads, 56 i each, float4 over o ---
    {
        int grp = t >> 6, o4 = (t & 63) * 4;
        const float* Up = g_UT + grp * 56 * 256;
        const float* hp = hs + grp * 56;
        float4 acc = make_float4(0.f, 0.f, 0.f, 0.f);
        #pragma unroll
        for (int blk = 0; blk < 7; blk++) {
            float4 w4[8];
            #pragma unroll
            for (int j = 0; j < 8; j++)
                w4[j] = __ldg((const float4*)(Up + (blk * 8 + j) * 256 + o4));
            #pragma unroll
            for (int j = 0; j < 8; j++) {
                float h = hp[blk * 8 + j];
                acc.x += h * w4[j].x; acc.y += h * w4[j].y;
                acc.z += h * w4[j].z; acc.w += h * w4[j].w;
            }
        }
        *(float4*)(&part[grp][o4]) = acc;
    }
    __syncthreads();

    float tp = 0.f;
    if (t < 256) {
        #pragma unroll
        for (int s = 0; s < 8; s++) tp += part[s][t];
        tp += g_B0[t] + dcompb[t];
    }

    // --- LN(256) + GELU -> tokens ---
    float mean = bsum512((t < 256) ? tp : 0.f, red) * (1.f / 256.f);
    float dv = tp - mean;
    float var = bsum512((t < 256) ? dv * dv : 0.f, red) * (1.f / 256.f);
    float rstd = rsqrtf(var + 1e-5f);
    float* tokp = &part[0][0];   // reuse shared
    if (t < 256) {
        float tv = gelu_exact(dv * rstd * ds_g[t] + ds_b[t]);
        tokp[t] = tv;
        g_tok[b * 256 + t] = tv;
    }
    __syncthreads();

    // --- gating: warp e (first 8 warps) computes logit e ---
    if (t < 256) {
        const float* te = task_embed + task_ids[b] * 256;
        float s = 0.f;
        for (int o = lane; o < 256; o += 32) {
            s += tokp[o] * __ldg(gate_w + o * 8 + w);
            s += __ldg(te + o) * __ldg(gate_w + (256 + o) * 8 + w);
        }
        #pragma unroll
        for (int off = 16; off; off >>= 1) s += __shfl_xor_sync(0xffffffffu, s, off);
        if (lane == 0) gsh[w] = s + gate_b[w];
    }
    __syncthreads();
    if (t == 0) {
        float v1 = -1e30f; int e1 = 0;
        #pragma unroll
        for (int e = 0; e < 8; e++) if (gsh[e] > v1) { v1 = gsh[e]; e1 = e; }
        float v2 = -1e30f; int e2 = 0;
        #pragma unroll
        for (int e = 0; e < 8; e++) if (e != e1 && gsh[e] > v2) { v2 = gsh[e]; e2 = e; }
        float g1 = 1.f / (1.f + expf(v2 - v1));
        g_esel[b * 2 + 0] = e1; g_esel[b * 2 + 1] = e2;
        g_gc[b * 4 + 0] = g1;
        g_gc[b * 4 + 1] = 1.f - g1;
        g_gc[b * 4 + 2] = 1.f - g1;   // omega = 1 - max(gates) = 1 - g1 (g1 >= 0.5)
    }
}

// ---------------------------------------------------------------------------
// K4b: the three 256x256 GEMVs (expert1, expert2, universal) + GELU.
// grid (3, 16) = (gemv, b), 512 threads: 8 d-slices x 64 o-quads, batched MLP=8
// ---------------------------------------------------------------------------
__global__ void k4b(const float* __restrict__ exp_w,
                    const float* __restrict__ exp_b,
                    const float* __restrict__ uni_w,
                    const float* __restrict__ uni_b) {
    int g = blockIdx.x, b = blockIdx.y, t = threadIdx.x;
    __shared__ float tok[256];
    __shared__ float part[8][256];
    if (t < 256) tok[t] = g_tok[b * 256 + t];
    __syncthreads();

    const float* Wb; const float* Bb;
    if (g < 2) {
        int e = g_esel[b * 2 + g];
        Wb = exp_w + (long)e * 65536;
        Bb = exp_b + e * 256;
    } else {
        Wb = uni_w; Bb = uni_b;
    }

    int f4 = (t & 63) * 4, ds = t >> 6;      // ds in 0..7, 32 d each
    int d0 = ds * 32;
    float4 acc = make_float4(0.f, 0.f, 0.f, 0.f);
    #pragma unroll
    for (int blk = 0; blk < 4; blk++) {
        float4 w4[8];
        #pragma unroll
        for (int j = 0; j < 8; j++)
            w4[j] = __ldg((const float4*)(Wb + (d0 + blk * 8 + j) * 256 + f4));
        #pragma unroll
        for (int j = 0; j < 8; j++) {
            float tv = tok[d0 + blk * 8 + j];
            acc.x += tv * w4[j].x; acc.y += tv * w4[j].y;
            acc.z += tv * w4[j].z; acc.w += tv * w4[j].w;
        }
    }
    *(float4*)(&part[ds][f4]) = acc;
    __syncthreads();

    if (t < 256) {
        float s = 0.f;
        #pragma unroll
        for (int p = 0; p < 8; p++) s += part[p][t];
        g_y[(b * 3 + g) * 256 + t] = gelu_exact(s + Bb[t]);
    }
}

// ---------------------------------------------------------------------------
// K4c: combine gated outputs + final LN. grid 16, 256 threads
// ---------------------------------------------------------------------------
__global__ void k4c(const float* __restrict__ out_g,
                    const float* __restrict__ out_b,
                    float* __restrict__ out) {
    int b = blockIdx.x, t = threadIdx.x;
    __shared__ float red[32];
    float g0 = g_gc[b * 4 + 0], g1 = g_gc[b * 4 + 1], om = g_gc[b * 4 + 2];
    const float* y = g_y + b * 3 * 256;
    float val = g0 * y[t] + g1 * y[256 + t] + om * y[512 + t];
    float m = bsum256(val, red) * (1.f / 256.f);
    float dv = val - m;
    float v = bsum256(dv * dv, red) * (1.f / 256.f);
    float rs = rsqrtf(v + 1e-5f);
    out[b * 256 + t] = dv * rs * out_g[t] + out_b[t];
}

// ---------------------------------------------------------------------------
extern "C" void kernel_launch(void* const* d_in, const int* in_sizes, int n_in,
                              void* d_out, int out_size) {
    const float* x_stream   = (const float*)d_in[0];
    const int*   task_ids   = (const int*)  d_in[1];
    const float* conv_w     = (const float*)d_in[2];
    const float* conv_b     = (const float*)d_in[3];
    const float* cls_token  = (const float*)d_in[4];
    const float* tok_g      = (const float*)d_in[5];
    const float* tok_b      = (const float*)d_in[6];
    const float* ds_conv_w  = (const float*)d_in[7];
    const float* ds_conv_b  = (const float*)d_in[8];
    const float* ds_comp_w  = (const float*)d_in[9];
    const float* ds_comp_b  = (const float*)d_in[10];
    const float* ds_g       = (const float*)d_in[11];
    const float* ds_b       = (const float*)d_in[12];
    const float* task_embed = (const float*)d_in[13];
    const float* gate_w     = (const float*)d_in[14];
    const float* gate_b     = (const float*)d_in[15];
    const float* exp_w      = (const float*)d_in[16];
    const float* exp_b      = (const float*)d_in[17];
    const float* uni_w      = (const float*)d_in[18];
    const float* uni_b      = (const float*)d_in[19];
    const float* out_g      = (const float*)d_in[20];
    const float* out_b      = (const float*)d_in[21];
    float* out = (float*)d_out;

    k0_transpose<<<72, 256>>>(conv_w);
    k1_conv_pool<<<dim3(6, 16), 192>>>(x_stream, conv_b);
    k3_fold<<<256, 256>>>(ds_comp_w, ds_conv_w, ds_conv_b);
    k4a<<<16, 512>>>(cls_token, tok_g, tok_b, task_ids, task_embed,
                     ds_comp_b, ds_g, ds_b, gate_w, gate_b);
    k4b<<<dim3(3, 16), 512>>>(exp_w, exp_b, uni_w, uni_b);
    k4c<<<16, 256>>>(out_g, out_b, out);
}

// round 5
// speedup vs baseline: 2.4555x; 1.2385x over previous
#include <cuda_runtime.h>
#include <cuda_bf16.h>
#include <math.h>

// B=16, C=22, L=3000, D=64, D2=256, E=8, T=4, K=13
// Only output token n=0 matters -> only tokens n=0..6 (conv q=0..17, x[:, :, 0..40]).

__device__ float g_cwT[286 * 64];        // transposed conv_w: [(c*13+k)][d]
__device__ float g_hln[16 * 448];        // LN'd tokens [b][n=0..6][d]   (n=0 = cls)
__device__ float g_tp[16 * 256];         // tokens_pre [b][o]

__device__ __forceinline__ float gelu_exact(float x) {
    return 0.5f * x * (1.0f + erff(x * 0.70710678118654752f));
}

// ---------------------------------------------------------------------------
// K0: transpose conv_w [64][286] -> g_cwT [(c*13+k)][64]
// ---------------------------------------------------------------------------
__global__ void k0_transpose(const float* __restrict__ cw) {
    int idx = blockIdx.x * 256 + threadIdx.x;
    if (idx < 286 * 64) {
        int ck = idx >> 6, d = idx & 63;
        g_cwT[idx] = __ldg(cw + d * 286 + ck);
    }
}

// ---------------------------------------------------------------------------
// K1: conv1d(stride2,pad6)+GELU+maxpool(3,3)+token LN (+cls LN in p==0 blocks)
// grid (6, 16) = (p, b), 192 threads = (qi 0..2) x (d 0..63)
// ---------------------------------------------------------------------------
__global__ void __launch_bounds__(192) k1_conv_pool_ln(
        const float* __restrict__ x,
        const float* __restrict__ cb,
        const float* __restrict__ cls,
        const float* __restrict__ tg,
        const float* __restrict__ tb) {
    __shared__ float xs[22][23];
    __shared__ float cv[3][64];
    int p = blockIdx.x, b = blockIdx.y, t = threadIdx.x;
    int base = 6 * p - 6;
    for (int l = t; l < 22 * 23; l += 192) {
        int c = l / 23, j = l - c * 23;
        int xi = base + j;
        xs[c][j] = (xi >= 0) ? x[(b * 22 + c) * 3000 + xi] : 0.f;
    }
    __syncthreads();
    {
        int qi = t / 64, d = t & 63;
        float acc = cb[d];
        #pragma unroll 2
        for (int c = 0; c < 22; c++) {
            float wv[13];
            #pragma unroll
            for (int k = 0; k < 13; k++)
                wv[k] = __ldg(g_cwT + (c * 13 + k) * 64 + d);
            #pragma unroll
            for (int k = 0; k < 13; k++)
                acc += wv[k] * xs[c][2 * qi + k];
        }
        cv[qi][d] = gelu_exact(acc);
    }
    __syncthreads();
    if (t < 32) {
        // pooled token LN (token n = p+1), warp 0; 2 elems per lane
        float v0 = fmaxf(fmaxf(cv[0][t], cv[1][t]), cv[2][t]);
        float v1 = fmaxf(fmaxf(cv[0][t + 32], cv[1][t + 32]), cv[2][t + 32]);
        float s = v0 + v1;
        #pragma unroll
        for (int off = 16; off; off >>= 1) s += __shfl_xor_sync(0xffffffffu, s, off);
        float mean = s * (1.f / 64.f);
        float d0 = v0 - mean, d1 = v1 - mean;
        float q = d0 * d0 + d1 * d1;
        #pragma unroll
        for (int off = 16; off; off >>= 1) q += __shfl_xor_sync(0xffffffffu, q, off);
        float rstd = rsqrtf(q * (1.f / 64.f) + 1e-5f);
        float* dst = g_hln + b * 448 + (p + 1) * 64;
        dst[t]      = d0 * rstd * tg[t]      + tb[t];
        dst[t + 32] = d1 * rstd * tg[t + 32] + tb[t + 32];
    } else if (p == 0 && t < 64) {
        // cls token LN (token n = 0), warp 1
        int lane = t - 32;
        float v0 = cls[lane], v1 = cls[lane + 32];
        float s = v0 + v1;
        #pragma unroll
        for (int off = 16; off; off >>= 1) s += __shfl_xor_sync(0xffffffffu, s, off);
        float mean = s * (1.f / 64.f);
        float d0 = v0 - mean, d1 = v1 - mean;
        float q = d0 * d0 + d1 * d1;
        #pragma unroll
        for (int off = 16; off; off >>= 1) q += __shfl_xor_sync(0xffffffffu, q, off);
        float rstd = rsqrtf(q * (1.f / 64.f) + 1e-5f);
        float* dst = g_hln + b * 448;
        dst[lane]      = d0 * rstd * tg[lane]      + tb[lane];
        dst[lane + 32] = d1 * rstd * tg[lane + 32] + tb[lane + 32];
    }
}

// ---------------------------------------------------------------------------
// K3 fused: fold ds_conv into ds_comp_w AND apply to tokens directly.
//   tokens_pre[b,o] = sum_{k<7,d} U[o,k,d]*hln[b,k,d] + sum_d U[o,7,d] + dcompb[o]
//   where U[o,k,d] = sum_c W[o,c,d]*w1p[c,k],
//         w1p[c,k] = ds_conv_w[c,6+k] (k<7), ds_conv_b[c] (k==7)
// Streams W (16.8MB) exactly once. grid 256 (o), 512 threads = 8 cgrp x 64 d
// ---------------------------------------------------------------------------
__global__ void __launch_bounds__(512) k3_fused(
        const float* __restrict__ W,
        const float* __restrict__ w1,
        const float* __restrict__ dcb,
        const float* __restrict__ dcompb) {
    __shared__ float w1s[256 * 8];    // [c][k]; k=7 slot holds dcb[c]
    __shared__ float up[8][8][64];    // [cgrp][k][d] partials
    __shared__ float red[16][16];     // [warp][b]
    int o = blockIdx.x, t = threadIdx.x;
    int w = t >> 5, lane = t & 31;

    for (int l = t; l < 2048; l += 512) {
        int c = l >> 3, k = l & 7;
        w1s[l] = (k < 7) ? __ldg(w1 + c * 13 + 6 + k) : __ldg(dcb + c);
    }
    __syncthreads();

    int cg = t >> 6, d = t & 63;
    int c0 = cg * 32;
    float u[8] = {0.f, 0.f, 0.f, 0.f, 0.f, 0.f, 0.f, 0.f};
    const float* Wo = W + (long)o * 16384 + (long)c0 * 64 + d;
    #pragma unroll
    for (int blk = 0; blk < 4; blk++) {
        float wv[8];
        #pragma unroll
        for (int j = 0; j < 8; j++)
            wv[j] = __ldg(Wo + (blk * 8 + j) * 64);
        #pragma unroll
        for (int j = 0; j < 8; j++) {
            const float4* wr = (const float4*)(w1s + (c0 + blk * 8 + j) * 8);
            float4 wa = wr[0], wb = wr[1];
            u[0] += wv[j] * wa.x; u[1] += wv[j] * wa.y;
            u[2] += wv[j] * wa.z; u[3] += wv[j] * wa.w;
            u[4] += wv[j] * wb.x; u[5] += wv[j] * wb.y;
            u[6] += wv[j] * wb.z; u[7] += wv[j] * wb.w;
        }
    }
    #pragma unroll
    for (int k = 0; k < 8; k++) up[cg][k][d] = u[k];
    __syncthreads();

    // phase B: thread = (kk, d); kk<7 dot with hln, kk==7 contributes constant
    int kk = t >> 6;
    float uf = 0.f;
    #pragma unroll
    for (int g = 0; g < 8; g++) uf += up[g][kk][d];

    float tpv[16];
    if (kk < 7) {
        const float* hp = g_hln + kk * 64 + d;
        float hv[16];
        #pragma unroll
        for (int b = 0; b < 16; b++) hv[b] = __ldg(hp + b * 448);
        #pragma unroll
        for (int b = 0; b < 16; b++) tpv[b] = uf * hv[b];
    } else {
        #pragma unroll
        for (int b = 0; b < 16; b++) tpv[b] = uf;
    }
    #pragma unroll
    for (int b = 0; b < 16; b++) {
        #pragma unroll
        for (int off = 16; off; off >>= 1)
            tpv[b] += __shfl_xor_sync(0xffffffffu, tpv[b], off);
    }
    if (lane < 16) red[w][lane] = tpv[lane];
    __syncthreads();
    if (t < 16) {
        float s = 0.f;
        #pragma unroll
        for (int w2 = 0; w2 < 16; w2++) s += red[w2][t];
        g_tp[t * 256 + o] = s + __ldg(dcompb + o);
    }
}

// ---------------------------------------------------------------------------
// block-wide sum for 768 threads
// ---------------------------------------------------------------------------
__device__ __forceinline__ float bsum768(float v, float* red) {
    #pragma unroll
    for (int off = 16; off; off >>= 1) v += __shfl_xor_sync(0xffffffffu, v, off);
    int w = threadIdx.x >> 5;
    if ((threadIdx.x & 31) == 0) red[w] = v;
    __syncthreads();
    if (threadIdx.x < 32) {
        float x = (threadIdx.x < 24) ? red[threadIdx.x] : 0.f;
        #pragma unroll
        for (int off = 16; off; off >>= 1) x += __shfl_xor_sync(0xffffffffu, x, off);
        if (threadIdx.x == 0) red[0] = x;
    }
    __syncthreads();
    float r = red[0];
    __syncthreads();
    return r;
}

// ---------------------------------------------------------------------------
// K4 fused: LN(256)+GELU -> gating -> 3 concurrent 256x256 GEMVs -> final LN
// grid 16 (b), 768 threads (3 GEMVs x 4 d-slices x 64 o-quads)
// ---------------------------------------------------------------------------
__global__ void __launch_bounds__(768) k4_fused(
        const int* __restrict__ task_ids,
        const float* __restrict__ task_embed,
        const float* __restrict__ ds_g,
        const float* __restrict__ ds_b,
        const float* __restrict__ gate_w,
        const float* __restrict__ gate_b,
        const float* __restrict__ exp_w,
        const float* __restrict__ exp_b,
        const float* __restrict__ uni_w,
        const float* __restrict__ uni_b,
        const float* __restrict__ out_g,
        const float* __restrict__ out_b,
        float* __restrict__ out) {
    int b = blockIdx.x, t = threadIdx.x;
    int w = t >> 5, lane = t & 31;
    __shared__ float tok[256];
    __shared__ float part[12][256];
    __shared__ float red[32];
    __shared__ float gsh[8];
    __shared__ float gco[4];
    __shared__ int esel[2];

    // --- LN(256) + GELU -> tokens ---
    float tp = (t < 256) ? g_tp[b * 256 + t] : 0.f;
    float mean = bsum768(tp, red) * (1.f / 256.f);
    float dv = tp - mean;
    float var = bsum768((t < 256) ? dv * dv : 0.f, red) * (1.f / 256.f);
    float rstd = rsqrtf(var + 1e-5f);
    if (t < 256) tok[t] = gelu_exact(dv * rstd * ds_g[t] + ds_b[t]);
    __syncthreads();

    // --- gating: warps 0..7 compute logits 0..7 ---
    if (t < 256) {
        const float* te = task_embed + task_ids[b] * 256;
        float s = 0.f;
        for (int o = lane; o < 256; o += 32) {
            s += tok[o] * __ldg(gate_w + o * 8 + w);
            s += __ldg(te + o) * __ldg(gate_w + (256 + o) * 8 + w);
        }
        #pragma unroll
        for (int off = 16; off; off >>= 1) s += __shfl_xor_sync(0xffffffffu, s, off);
        if (lane == 0) gsh[w] = s + gate_b[w];
    }
    __syncthreads();
    if (t == 0) {
        float v1 = -1e30f; int e1 = 0;
        #pragma unroll
        for (int e = 0; e < 8; e++) if (gsh[e] > v1) { v1 = gsh[e]; e1 = e; }
        float v2 = -1e30f; int e2 = 0;
        #pragma unroll
        for (int e = 0; e < 8; e++) if (e != e1 && gsh[e] > v2) { v2 = gsh[e]; e2 = e; }
        float g1 = 1.f / (1.f + expf(v2 - v1));
        esel[0] = e1; esel[1] = e2;
        gco[0] = g1; gco[1] = 1.f - g1; gco[2] = 1.f - g1;  // omega = 1 - max gate
    }
    __syncthreads();

    // --- 3 GEMVs concurrently: g = t>>8 ---
    {
        int g = t >> 8, tid2 = t & 255;
        int ds = tid2 >> 6, f4 = (tid2 & 63) * 4, d0 = ds * 64;
        const float* Wb = (g < 2) ? exp_w + (long)esel[g] * 65536 : uni_w;
        float4 acc = make_float4(0.f, 0.f, 0.f, 0.f);
        #pragma unroll
        for (int blk = 0; blk < 8; blk++) {
            float4 w4[8];
            #pragma unroll
            for (int j = 0; j < 8; j++)
                w4[j] = __ldg((const float4*)(Wb + (d0 + blk * 8 + j) * 256 + f4));
            #pragma unroll
            for (int j = 0; j < 8; j++) {
                float tv = tok[d0 + blk * 8 + j];
                acc.x += tv * w4[j].x; acc.y += tv * w4[j].y;
                acc.z += tv * w4[j].z; acc.w += tv * w4[j].w;
            }
        }
        *(float4*)(&part[g * 4 + ds][f4]) = acc;
    }
    __syncthreads();

    // --- combine + final LN ---
    float val = 0.f;
    if (t < 256) {
        float s0 = part[0][t] + part[1][t] + part[2][t] + part[3][t];
        float s1 = part[4][t] + part[5][t] + part[6][t] + part[7][t];
        float s2 = part[8][t] + part[9][t] + part[10][t] + part[11][t];
        float y0 = gelu_exact(s0 + __ldg(exp_b + esel[0] * 256 + t));
        float y1 = gelu_exact(s1 + __ldg(exp_b + esel[1] * 256 + t));
        float y2 = gelu_exact(s2 + __ldg(uni_b + t));
        val = gco[0] * y0 + gco[1] * y1 + gco[2] * y2;
    }
    float m2 = bsum768(val, red) * (1.f / 256.f);
    float d2 = val - m2;
    float v2s = bsum768((t < 256) ? d2 * d2 : 0.f, red) * (1.f / 256.f);
    float rs2 = rsqrtf(v2s + 1e-5f);
    if (t < 256) out[b * 256 + t] = d2 * rs2 * out_g[t] + out_b[t];
}

// ---------------------------------------------------------------------------
extern "C" void kernel_launch(void* const* d_in, const int* in_sizes, int n_in,
                              void* d_out, int out_size) {
    const float* x_stream   = (const float*)d_in[0];
    const int*   task_ids   = (const int*)  d_in[1];
    const float* conv_w     = (const float*)d_in[2];
    const float* conv_b     = (const float*)d_in[3];
    const float* cls_token  = (const float*)d_in[4];
    const float* tok_g      = (const float*)d_in[5];
    const float* tok_b      = (const float*)d_in[6];
    const float* ds_conv_w  = (const float*)d_in[7];
    const float* ds_conv_b  = (const float*)d_in[8];
    const float* ds_comp_w  = (const float*)d_in[9];
    const float* ds_comp_b  = (const float*)d_in[10];
    const float* ds_g       = (const float*)d_in[11];
    const float* ds_b       = (const float*)d_in[12];
    const float* task_embed = (const float*)d_in[13];
    const float* gate_w     = (const float*)d_in[14];
    const float* gate_b     = (const float*)d_in[15];
    const float* exp_w      = (const float*)d_in[16];
    const float* exp_b      = (const float*)d_in[17];
    const float* uni_w      = (const float*)d_in[18];
    const float* uni_b      = (const float*)d_in[19];
    const float* out_g      = (const float*)d_in[20];
    const float* out_b      = (const float*)d_in[21];
    float* out = (float*)d_out;

    k0_transpose<<<72, 256>>>(conv_w);
    k1_conv_pool_ln<<<dim3(6, 16), 192>>>(x_stream, conv_b, cls_token, tok_g, tok_b);
    k3_fused<<<256, 512>>>(ds_comp_w, ds_conv_w, ds_conv_b, ds_comp_b);
    k4_fused<<<16, 768>>>(task_ids, task_embed, ds_g, ds_b, gate_w, gate_b,
                          exp_w, exp_b, uni_w, uni_b, out_g, out_b, out);
}

// round 6
// speedup vs baseline: 3.4842x; 1.4189x over previous
#include <cuda_runtime.h>
#include <cuda_bf16.h>
#include <math.h>

// B=16, C=22, L=3000, D=64, D2=256, E=8, T=4, K=13
// Only output token n=0 matters -> only tokens n=0..6 (conv q=0..17, x[:, :, 0..40]).

__device__ float g_cwT[286 * 64];        // transposed conv_w: [(c*13+k)][d]
__device__ float g_hln[16 * 448];        // LN'd tokens [b][n=0..6][d]   (n=0 = cls)
__device__ float g_tp[16 * 256];         // tokens_pre [b][o]
__device__ float g_tok[16 * 256];        // post LN+GELU tokens
__device__ int   g_esel[16 * 2];         // selected experts
__device__ float g_gc[16 * 4];           // gate coefs {g1, 1-g1, omega}
__device__ float g_y[16 * 3 * 256];      // gated GEMV outputs

__device__ __forceinline__ float gelu_exact(float x) {
    return 0.5f * x * (1.0f + erff(x * 0.70710678118654752f));
}

// ---------------------------------------------------------------------------
// K0: transpose conv_w [64][286] -> g_cwT [(c*13+k)][64]; coalesced reads
// grid 64 (d), 286 threads (ck)
// ---------------------------------------------------------------------------
__global__ void k0_transpose(const float* __restrict__ cw) {
    int d = blockIdx.x, ck = threadIdx.x;
    if (ck < 286) g_cwT[ck * 64 + d] = __ldg(cw + d * 286 + ck);
}

// ---------------------------------------------------------------------------
// K1: conv1d(stride2,pad6)+GELU+maxpool(3,3)+token LN (+cls LN in p==0 blocks)
// grid (6, 16) = (p, b), 192 threads = (qi 0..2) x (d 0..63)
// ---------------------------------------------------------------------------
__global__ void __launch_bounds__(192) k1_conv_pool_ln(
        const float* __restrict__ x,
        const float* __restrict__ cb,
        const float* __restrict__ cls,
        const float* __restrict__ tg,
        const float* __restrict__ tb) {
    __shared__ float xs[22][23];
    __shared__ float cv[3][64];
    int p = blockIdx.x, b = blockIdx.y, t = threadIdx.x;
    int base = 6 * p - 6;
    for (int l = t; l < 22 * 23; l += 192) {
        int c = l / 23, j = l - c * 23;
        int xi = base + j;
        xs[c][j] = (xi >= 0) ? x[(b * 22 + c) * 3000 + xi] : 0.f;
    }
    __syncthreads();
    {
        int qi = t / 64, d = t & 63;
        float acc = cb[d];
        #pragma unroll
        for (int c = 0; c < 22; c += 2) {
            float wv[26];      // two channels' taps batched -> MLP 26
            #pragma unroll
            for (int k = 0; k < 26; k++)
                wv[k] = __ldg(g_cwT + (c * 13 + k) * 64 + d);
            #pragma unroll
            for (int k = 0; k < 13; k++) acc += wv[k] * xs[c][2 * qi + k];
            #pragma unroll
            for (int k = 0; k < 13; k++) acc += wv[13 + k] * xs[c + 1][2 * qi + k];
        }
        cv[qi][d] = gelu_exact(acc);
    }
    __syncthreads();
    if (t < 32) {
        float v0 = fmaxf(fmaxf(cv[0][t], cv[1][t]), cv[2][t]);
        float v1 = fmaxf(fmaxf(cv[0][t + 32], cv[1][t + 32]), cv[2][t + 32]);
        float s = v0 + v1;
        #pragma unroll
        for (int off = 16; off; off >>= 1) s += __shfl_xor_sync(0xffffffffu, s, off);
        float mean = s * (1.f / 64.f);
        float d0 = v0 - mean, d1 = v1 - mean;
        float q = d0 * d0 + d1 * d1;
        #pragma unroll
        for (int off = 16; off; off >>= 1) q += __shfl_xor_sync(0xffffffffu, q, off);
        float rstd = rsqrtf(q * (1.f / 64.f) + 1e-5f);
        float* dst = g_hln + b * 448 + (p + 1) * 64;
        dst[t]      = d0 * rstd * tg[t]      + tb[t];
        dst[t + 32] = d1 * rstd * tg[t + 32] + tb[t + 32];
    } else if (p == 0 && t < 64) {
        int lane = t - 32;
        float v0 = cls[lane], v1 = cls[lane + 32];
        float s = v0 + v1;
        #pragma unroll
        for (int off = 16; off; off >>= 1) s += __shfl_xor_sync(0xffffffffu, s, off);
        float mean = s * (1.f / 64.f);
        float d0 = v0 - mean, d1 = v1 - mean;
        float q = d0 * d0 + d1 * d1;
        #pragma unroll
        for (int off = 16; off; off >>= 1) q += __shfl_xor_sync(0xffffffffu, q, off);
        float rstd = rsqrtf(q * (1.f / 64.f) + 1e-5f);
        float* dst = g_hln + b * 448;
        dst[lane]      = d0 * rstd * tg[lane]      + tb[lane];
        dst[lane + 32] = d1 * rstd * tg[lane + 32] + tb[lane + 32];
    }
}

// ---------------------------------------------------------------------------
// K3 fused: fold ds_conv into ds_comp_w AND apply to tokens directly.
// grid 256 (o), 512 threads = 8 cgrp x 64 d; phase A batches 16 loads (MLP 16)
// ---------------------------------------------------------------------------
__global__ void __launch_bounds__(512) k3_fused(
        const float* __restrict__ W,
        const float* __restrict__ w1,
        const float* __restrict__ dcb,
        const float* __restrict__ dcompb) {
    __shared__ float w1s[256 * 8];    // [c][k]; k=7 slot holds dcb[c]
    __shared__ float up[8][8][64];    // [cgrp][k][d] partials
    __shared__ float red[16][16];     // [warp][b]
    int o = blockIdx.x, t = threadIdx.x;
    int w = t >> 5, lane = t & 31;

    for (int l = t; l < 2048; l += 512) {
        int c = l >> 3, k = l & 7;
        w1s[l] = (k < 7) ? __ldg(w1 + c * 13 + 6 + k) : __ldg(dcb + c);
    }
    __syncthreads();

    int cg = t >> 6, d = t & 63;
    int c0 = cg * 32;
    float u[8] = {0.f, 0.f, 0.f, 0.f, 0.f, 0.f, 0.f, 0.f};
    const float* Wo = W + (long)o * 16384 + (long)c0 * 64 + d;
    #pragma unroll
    for (int half = 0; half < 2; half++) {
        float wv[16];
        #pragma unroll
        for (int j = 0; j < 16; j++)
            wv[j] = __ldg(Wo + (half * 16 + j) * 64);
        #pragma unroll
        for (int j = 0; j < 16; j++) {
            const float4* wr = (const float4*)(w1s + (c0 + half * 16 + j) * 8);
            float4 wa = wr[0], wb = wr[1];
            u[0] += wv[j] * wa.x; u[1] += wv[j] * wa.y;
            u[2] += wv[j] * wa.z; u[3] += wv[j] * wa.w;
            u[4] += wv[j] * wb.x; u[5] += wv[j] * wb.y;
            u[6] += wv[j] * wb.z; u[7] += wv[j] * wb.w;
        }
    }
    #pragma unroll
    for (int k = 0; k < 8; k++) up[cg][k][d] = u[k];
    __syncthreads();

    // phase B: thread = (kk, d); kk<7 dot with hln, kk==7 contributes constant
    int kk = t >> 6;
    float uf = 0.f;
    #pragma unroll
    for (int g = 0; g < 8; g++) uf += up[g][kk][d];

    float tpv[16];
    if (kk < 7) {
        const float* hp = g_hln + kk * 64 + d;
        float hv[16];
        #pragma unroll
        for (int b = 0; b < 16; b++) hv[b] = __ldg(hp + b * 448);
        #pragma unroll
        for (int b = 0; b < 16; b++) tpv[b] = uf * hv[b];
    } else {
        #pragma unroll
        for (int b = 0; b < 16; b++) tpv[b] = uf;
    }
    #pragma unroll
    for (int b = 0; b < 16; b++) {
        #pragma unroll
        for (int off = 16; off; off >>= 1)
            tpv[b] += __shfl_xor_sync(0xffffffffu, tpv[b], off);
    }
    if (lane < 16) red[w][lane] = tpv[lane];
    __syncthreads();
    if (t < 16) {
        float s = 0.f;
        #pragma unroll
        for (int w2 = 0; w2 < 16; w2++) s += red[w2][t];
        g_tp[t * 256 + o] = s + __ldg(dcompb + o);
    }
}

// ---------------------------------------------------------------------------
__device__ __forceinline__ float bsum256(float v, float* red) {
    #pragma unroll
    for (int off = 16; off; off >>= 1) v += __shfl_xor_sync(0xffffffffu, v, off);
    int w = threadIdx.x >> 5;
    if ((threadIdx.x & 31) == 0) red[w] = v;
    __syncthreads();
    if (threadIdx.x < 32) {
        float x = (threadIdx.x < 8) ? red[threadIdx.x] : 0.f;
        #pragma unroll
        for (int off = 4; off; off >>= 1) x += __shfl_xor_sync(0xffffffffu, x, off);
        if (threadIdx.x == 0) red[0] = x;
    }
    __syncthreads();
    float r = red[0];
    __syncthreads();
    return r;
}

// ---------------------------------------------------------------------------
// KA: LN(256)+GELU -> tokens; gating (top-2). grid 16 (b), 256 threads
// ---------------------------------------------------------------------------
__global__ void __launch_bounds__(256) kA_gate(
        const int* __restrict__ task_ids,
        const float* __restrict__ task_embed,
        const float* __restrict__ ds_g,
        const float* __restrict__ ds_b,
        const float* __restrict__ gate_w,
        const float* __restrict__ gate_b) {
    int b = blockIdx.x, t = threadIdx.x;
    int w = t >> 5, lane = t & 31;
    __shared__ float tok[256];
    __shared__ float red[32];
    __shared__ float gsh[8];

    float tp = g_tp[b * 256 + t];
    float mean = bsum256(tp, red) * (1.f / 256.f);
    float dv = tp - mean;
    float var = bsum256(dv * dv, red) * (1.f / 256.f);
    float rstd = rsqrtf(var + 1e-5f);
    float tv = gelu_exact(dv * rstd * ds_g[t] + ds_b[t]);
    tok[t] = tv;
    g_tok[b * 256 + t] = tv;
    __syncthreads();

    // gating: warp e computes logit e; batch the gate_w loads
    {
        const float* te = task_embed + task_ids[b] * 256;
        float s = 0.f;
        float gw[8], gv[8], tev[8];
        #pragma unroll
        for (int i = 0; i < 8; i++) {
            int o = lane + i * 32;
            gw[i]  = __ldg(gate_w + o * 8 + w);
            gv[i]  = __ldg(gate_w + (256 + o) * 8 + w);
            tev[i] = __ldg(te + o);
        }
        #pragma unroll
        for (int i = 0; i < 8; i++)
            s += tok[lane + i * 32] * gw[i] + tev[i] * gv[i];
        #pragma unroll
        for (int off = 16; off; off >>= 1) s += __shfl_xor_sync(0xffffffffu, s, off);
        if (lane == 0) gsh[w] = s + gate_b[w];
    }
    __syncthreads();
    if (t == 0) {
        float v1 = -1e30f; int e1 = 0;
        #pragma unroll
        for (int e = 0; e < 8; e++) if (gsh[e] > v1) { v1 = gsh[e]; e1 = e; }
        float v2 = -1e30f; int e2 = 0;
        #pragma unroll
        for (int e = 0; e < 8; e++) if (e != e1 && gsh[e] > v2) { v2 = gsh[e]; e2 = e; }
        float g1 = 1.f / (1.f + expf(v2 - v1));
        g_esel[b * 2 + 0] = e1; g_esel[b * 2 + 1] = e2;
        g_gc[b * 4 + 0] = g1;
        g_gc[b * 4 + 1] = 1.f - g1;
        g_gc[b * 4 + 2] = 1.f - g1;   // omega = 1 - max gate (g1 >= 0.5)
    }
}

// ---------------------------------------------------------------------------
// KB: 256x256 GEMV + GELU + gate scaling. grid (3,16), 512 threads.
// 8 d-slices x 64 o-quads; batch 16 float4 loads -> 2 exposed latency waves
// ---------------------------------------------------------------------------
__global__ void __launch_bounds__(512) kB_gemv(
        const float* __restrict__ exp_w,
        const float* __restrict__ exp_b,
        const float* __restrict__ uni_w,
        const float* __restrict__ uni_b) {
    int g = blockIdx.x, b = blockIdx.y, t = threadIdx.x;
    __shared__ float tok[256];
    __shared__ float part[8][256];
    if (t < 256) tok[t] = g_tok[b * 256 + t];
    __syncthreads();

    const float* Wb; const float* Bb;
    if (g < 2) {
        int e = g_esel[b * 2 + g];
        Wb = exp_w + (long)e * 65536;
        Bb = exp_b + e * 256;
    } else {
        Wb = uni_w; Bb = uni_b;
    }

    int ds = t >> 6, f4 = (t & 63) * 4;
    int d0 = ds * 32;
    float4 acc = make_float4(0.f, 0.f, 0.f, 0.f);
    #pragma unroll
    for (int blk = 0; blk < 2; blk++) {
        float4 w4[16];
        #pragma unroll
        for (int j = 0; j < 16; j++)
            w4[j] = __ldg((const float4*)(Wb + (d0 + blk * 16 + j) * 256 + f4));
        #pragma unroll
        for (int j = 0; j < 16; j++) {
            float tv = tok[d0 + blk * 16 + j];
            acc.x += tv * w4[j].x; acc.y += tv * w4[j].y;
            acc.z += tv * w4[j].z; acc.w += tv * w4[j].w;
        }
    }
    *(float4*)(&part[ds][f4]) = acc;
    __syncthreads();

    if (t < 256) {
        float s = 0.f;
        #pragma unroll
        for (int p = 0; p < 8; p++) s += part[p][t];
        float coef = g_gc[b * 4 + g];
        g_y[(b * 3 + g) * 256 + t] = coef * gelu_exact(s + __ldg(Bb + t));
    }
}

// ---------------------------------------------------------------------------
// KC: combine gated outputs + final LN. grid 16, 256 threads
// ---------------------------------------------------------------------------
__global__ void __launch_bounds__(256) kC_out(
        const float* __restrict__ out_g,
        const float* __restrict__ out_b,
        float* __restrict__ out) {
    int b = blockIdx.x, t = threadIdx.x;
    __shared__ float red[32];
    const float* y = g_y + b * 3 * 256;
    float val = y[t] + y[256 + t] + y[512 + t];
    float m = bsum256(val, red) * (1.f / 256.f);
    float dv = val - m;
    float v = bsum256(dv * dv, red) * (1.f / 256.f);
    float rs = rsqrtf(v + 1e-5f);
    out[b * 256 + t] = dv * rs * out_g[t] + out_b[t];
}

// ---------------------------------------------------------------------------
extern "C" void kernel_launch(void* const* d_in, const int* in_sizes, int n_in,
                              void* d_out, int out_size) {
    const float* x_stream   = (const float*)d_in[0];
    const int*   task_ids   = (const int*)  d_in[1];
    const float* conv_w     = (const float*)d_in[2];
    const float* conv_b     = (const float*)d_in[3];
    const float* cls_token  = (const float*)d_in[4];
    const float* tok_g      = (const float*)d_in[5];
    const float* tok_b      = (const float*)d_in[6];
    const float* ds_conv_w  = (const float*)d_in[7];
    const float* ds_conv_b  = (const float*)d_in[8];
    const float* ds_comp_w  = (const float*)d_in[9];
    const float* ds_comp_b  = (const float*)d_in[10];
    const float* ds_g       = (const float*)d_in[11];
    const float* ds_b       = (const float*)d_in[12];
    const float* task_embed = (const float*)d_in[13];
    const float* gate_w     = (const float*)d_in[14];
    const float* gate_b     = (const float*)d_in[15];
    const float* exp_w      = (const float*)d_in[16];
    const float* exp_b      = (const float*)d_in[17];
    const float* uni_w      = (const float*)d_in[18];
    const float* uni_b      = (const float*)d_in[19];
    const float* out_g      = (const float*)d_in[20];
    const float* out_b      = (const float*)d_in[21];
    float* out = (float*)d_out;

    k0_transpose<<<64, 286>>>(conv_w);
    k1_conv_pool_ln<<<dim3(6, 16), 192>>>(x_stream, conv_b, cls_token, tok_g, tok_b);
    k3_fused<<<256, 512>>>(ds_comp_w, ds_conv_w, ds_conv_b, ds_comp_b);
    kA_gate<<<16, 256>>>(task_ids, task_embed, ds_g, ds_b, gate_w, gate_b);
    kB_gemv<<<dim3(3, 16), 512>>>(exp_w, exp_b, uni_w, uni_b);
    kC_out<<<16, 256>>>(out_g, out_b, out);
}